// round 12
// baseline (speedup 1.0000x reference)
#include <cuda_runtime.h>
#include <cstddef>

#define NN 16384
#define CC 10000
#define DD 128
#define LR 0.5f

#define NVEC   (CC / 4)       // 2500 float4 per label row
#define SCANT  64             // threads per block (2 warps)
#define CHUNKV (SCANT * 2)    // 128 float4 = 2KB lockstep chunks (MLP=2)

#define EPI_BLKS    250       // last 250 blocks run the epilogue
#define CLS_PER_BLK 40        // 250 * 40 = 10000 classes
#define F4_PER_BLK  (CLS_PER_BLK * DD / 4)   // 1280 float4 per block

// Scratch (no cudaMalloc allowed). Zero-initialized at module load; the
// epilogue re-zeroes everything so each graph replay starts clean.
__device__ float g_sum[CC * DD];  // per-class sum of preds
__device__ float g_cnt[CC];      // per-class sample count
__device__ int   g_done = 0;     // scan blocks completed
__device__ int   g_fin  = 0;     // epilogue blocks completed

// ---------------------------------------------------------------------------
// One 64-thread block per sample.
// Phase 1: lockstep early-exit scan, 2KB chunks, 2 float4 in flight per
//          thread. ONE __syncthreads_or per chunk gives a uniform exit
//          predicate (no divergent-barrier hazard); s_cls is written at most
//          once, before the same barrier every reader crosses.
//          E[bytes/row] ~ (40KB + 2KB)/2 = 21KB.
// Phase 2: red-atomics of preds[n,:] into g_sum[class,:] (+count).
// Phase 3: release fence + g_done tick. The statically-chosen LAST 250
//          blocks then spin (t0 only, exponential backoff) until all 16384
//          ticks landed, and finalize a 40-class slice:
//            out = (1 - LR*cnt/(cnt+1))*center + (LR/(cnt+1))*sum
//          re-zeroing their slice of g_sum/g_cnt. Last epilogue finisher
//          resets the counters (all spins have exited by then).
// ---------------------------------------------------------------------------
__global__ void __launch_bounds__(SCANT) cl_fused_kernel(
    const float* __restrict__ labels,   // [N, C]
    const float* __restrict__ preds,    // [N, D]
    const float* __restrict__ center,   // [C, D]
    float* __restrict__ out)            // [C, D]
{
    __shared__ int s_cls;
    const int n = blockIdx.x;
    const int t = threadIdx.x;

    // ---- Phase 1: scan ----
    const float4* __restrict__ row =
        reinterpret_cast<const float4*>(labels + (size_t)n * CC);

    int cls = -1;
    #pragma unroll 1
    for (int base = 0; base < NVEC; base += CHUNKV) {
        const int i0 = base + t;
        const int i1 = base + t + SCANT;
        float4 v0, v1;
        const bool p0 = (i0 < NVEC);
        const bool p1 = (i1 < NVEC);
        if (p0) v0 = __ldg(&row[i0]);
        if (p1) v1 = __ldg(&row[i1]);

        int found = -1;
        if (p0) {
            if (v0.x != 0.0f)      found = 4 * i0 + 0;
            else if (v0.y != 0.0f) found = 4 * i0 + 1;
            else if (v0.z != 0.0f) found = 4 * i0 + 2;
            else if (v0.w != 0.0f) found = 4 * i0 + 3;
        }
        if (found < 0 && p1) {
            if (v1.x != 0.0f)      found = 4 * i1 + 0;
            else if (v1.y != 0.0f) found = 4 * i1 + 1;
            else if (v1.z != 0.0f) found = 4 * i1 + 2;
            else if (v1.w != 0.0f) found = 4 * i1 + 3;
        }

        if (found >= 0) s_cls = found;           // at most one write, ever
        if (__syncthreads_or(found >= 0)) {      // uniform exit predicate
            cls = s_cls;                         // visible: write pre-barrier
            break;
        }
    }

    // ---- Phase 2: accumulate (RED, no return) ----
    const float* __restrict__ pr = preds + (size_t)n * DD;
    atomicAdd(&g_sum[(size_t)cls * DD + t],         __ldg(&pr[t]));
    atomicAdd(&g_sum[(size_t)cls * DD + t + SCANT], __ldg(&pr[t + SCANT]));
    if (t == 0) atomicAdd(&g_cnt[cls], 1.0f);

    // Release: this block's REDs visible before its tick is observed.
    __threadfence();
    __syncthreads();
    if (t == 0) atomicAdd(&g_done, 1);

    // ---- Phase 3: epilogue (last EPI_BLKS blocks only) ----
    if (n < NN - EPI_BLKS) return;
    const int e = n - (NN - EPI_BLKS);           // 0..249, deterministic

    if (t == 0) {
        int ns = 64;
        while (*(volatile int*)&g_done != NN) {  // short window: tail drain
            __nanosleep(ns);
            if (ns < 2048) ns += ns;             // backoff: ~100x less L2 poll
        }
    }
    __syncthreads();
    __threadfence();                              // acquire before scratch reads

    const int base4 = e * F4_PER_BLK;
    const float4* __restrict__ gs = reinterpret_cast<const float4*>(g_sum);
    const float4* __restrict__ gc = reinterpret_cast<const float4*>(center);
    float4* __restrict__ po  = reinterpret_cast<float4*>(out);
    float4* __restrict__ gsw = reinterpret_cast<float4*>(g_sum);

    #pragma unroll 4
    for (int j = t; j < F4_PER_BLK; j += SCANT) {
        const int i4 = base4 + j;
        const int c  = i4 >> 5;                  // warp-uniform (32 f4/class)

        const float  cnt = __ldcg(&g_cnt[c]);
        const float4 s   = __ldcg(&gs[i4]);
        const float4 ce  = __ldg(&gc[i4]);

        const float inv = 1.0f / (cnt + 1.0f);
        const float a   = 1.0f - LR * cnt * inv; // coeff on center
        const float b   = LR * inv;              // coeff on sum

        float4 r;
        r.x = a * ce.x + b * s.x;
        r.y = a * ce.y + b * s.y;
        r.z = a * ce.z + b * s.z;
        r.w = a * ce.w + b * s.w;
        po[i4]  = r;
        gsw[i4] = make_float4(0.f, 0.f, 0.f, 0.f);   // clean for next replay
    }

    __syncthreads();                              // this block's cnt reads done
    if (t < CLS_PER_BLK) {
        g_cnt[e * CLS_PER_BLK + t] = 0.0f;        // slice-private classes
    }
    __threadfence();
    __syncthreads();
    if (t == 0) {
        const int f = atomicAdd(&g_fin, 1);
        if (f == EPI_BLKS - 1) {                  // last finisher resets
            g_done = 0;                           // all spins already exited
            g_fin  = 0;
        }
    }
}

// ---------------------------------------------------------------------------
// Launch. Inputs per metadata: embeded_preds [N*D], labels [N*C],
// center [C*D]. Output: updated_center [C*D] float32.
// ---------------------------------------------------------------------------
extern "C" void kernel_launch(void* const* d_in, const int* in_sizes, int n_in,
                              void* d_out, int out_size) {
    const float* preds  = (const float*)d_in[0];
    const float* labels = (const float*)d_in[1];
    const float* center = (const float*)d_in[2];
    float* out = (float*)d_out;

    (void)in_sizes; (void)n_in; (void)out_size;

    cl_fused_kernel<<<NN, SCANT>>>(labels, preds, center, out);
}

// round 13
// speedup vs baseline: 1.2927x; 1.2927x over previous
#include <cuda_runtime.h>
#include <cstddef>

#define NN 16384
#define CC 10000
#define DD 128
#define LR 0.5f

#define NVEC   (CC / 4)       // 2500 float4 per label row
#define SCANT  64             // threads per scan block (2 warps)
#define CHUNKV (SCANT * 3)    // 192 float4 = 3KB lockstep chunks (MLP=3)

// Scratch (no cudaMalloc allowed). Zero-initialized at module load; the
// finalize kernel re-zeroes after each use so every graph replay starts clean.
__device__ float g_sum[CC * DD];  // per-class sum of preds
__device__ float g_cnt[CC];      // per-class sample count

// ---------------------------------------------------------------------------
// Kernel 1: one 64-thread block per sample. Lockstep early-exit scan in 3KB
// chunks, 3 independent float4 loads in flight per thread (MLP=3). One
// __syncthreads_or per chunk gives a uniform exit predicate; s_cls is written
// at most once, always before the barrier every reader crosses.
// E[bytes/row] ~ (40KB + 3KB)/2 = 21.5KB. Labels are read with __ldcs
// (streamed once, evict-first) so L2 stays available for the g_sum REDs.
// Then red-atomics of preds[n,:] into the class accumulators.
// ---------------------------------------------------------------------------
__global__ void __launch_bounds__(SCANT) cl_scan_accum_kernel(
    const float* __restrict__ labels,   // [N, C]
    const float* __restrict__ preds)    // [N, D]
{
    __shared__ int s_cls;
    const int n = blockIdx.x;
    const int t = threadIdx.x;

    const float4* __restrict__ row =
        reinterpret_cast<const float4*>(labels + (size_t)n * CC);

    int cls = -1;
    #pragma unroll 1
    for (int base = 0; base < NVEC; base += CHUNKV) {
        const int i0 = base + t;
        const int i1 = base + t + SCANT;
        const int i2 = base + t + 2 * SCANT;

        float4 v0, v1, v2;
        const bool p0 = (i0 < NVEC);
        const bool p1 = (i1 < NVEC);
        const bool p2 = (i2 < NVEC);
        if (p0) v0 = __ldcs(&row[i0]);    // 3 loads issued back-to-back
        if (p1) v1 = __ldcs(&row[i1]);
        if (p2) v2 = __ldcs(&row[i2]);

        int found = -1;
        if (p0) {
            if (v0.x != 0.0f)      found = 4 * i0 + 0;
            else if (v0.y != 0.0f) found = 4 * i0 + 1;
            else if (v0.z != 0.0f) found = 4 * i0 + 2;
            else if (v0.w != 0.0f) found = 4 * i0 + 3;
        }
        if (found < 0 && p1) {
            if (v1.x != 0.0f)      found = 4 * i1 + 0;
            else if (v1.y != 0.0f) found = 4 * i1 + 1;
            else if (v1.z != 0.0f) found = 4 * i1 + 2;
            else if (v1.w != 0.0f) found = 4 * i1 + 3;
        }
        if (found < 0 && p2) {
            if (v2.x != 0.0f)      found = 4 * i2 + 0;
            else if (v2.y != 0.0f) found = 4 * i2 + 1;
            else if (v2.z != 0.0f) found = 4 * i2 + 2;
            else if (v2.w != 0.0f) found = 4 * i2 + 3;
        }

        if (found >= 0) s_cls = found;        // at most one write, ever
        if (__syncthreads_or(found >= 0)) {   // uniform exit decision
            cls = s_cls;                      // write was pre-barrier: visible
            break;
        }
    }

    // Accumulate preds[n,:] into g_sum[cls,:]; 64 threads x 2 dims.
    // Return value unused -> compiles to RED (no round trip).
    const float* __restrict__ pr = preds + (size_t)n * DD;
    atomicAdd(&g_sum[(size_t)cls * DD + t],         __ldg(&pr[t]));
    atomicAdd(&g_sum[(size_t)cls * DD + t + SCANT], __ldg(&pr[t + SCANT]));
    if (t == 0) atomicAdd(&g_cnt[cls], 1.0f);
}

// ---------------------------------------------------------------------------
// Kernel 2: finalize (float4 + 2x ILP) + re-zero scratch for next replay.
//   out[c] = (1 - LR*cnt/(cnt+1)) * center[c] + (LR/(cnt+1)) * sum[c]
// Thread handles float4 pair {2i, 2i+1}; each class spans 32 float4, so the
// pair is always within one class. A 256-thread block covers 16 whole
// classes -> g_cnt is block-private: read before the barrier, zero after.
// Scratch reads use __ldcg so the scan's L2 red-atomics are seen coherently.
// ---------------------------------------------------------------------------
__global__ void __launch_bounds__(256) cl_finalize_kernel(
    const float* __restrict__ center,   // [C, D]
    float* __restrict__ out)            // [C, D]
{
    const int i  = blockIdx.x * 256 + threadIdx.x;
    const int i4 = 2 * i;                       // first float4 index
    const int c  = i4 >> 5;                     // 32 float4 per class

    const float4* __restrict__ gs = reinterpret_cast<const float4*>(g_sum);
    const float4* __restrict__ gc = reinterpret_cast<const float4*>(center);

    const float cnt = __ldcg(&g_cnt[c]);
    const float4 s0 = __ldcg(&gs[i4]);
    const float4 s1 = __ldcg(&gs[i4 + 1]);
    const float4 c0 = __ldg(&gc[i4]);
    const float4 c1 = __ldg(&gc[i4 + 1]);

    const float inv = 1.0f / (cnt + 1.0f);
    const float a   = 1.0f - LR * cnt * inv;    // coeff on center
    const float b   = LR * inv;                 // coeff on sum

    float4 r0, r1;
    r0.x = a * c0.x + b * s0.x;  r0.y = a * c0.y + b * s0.y;
    r0.z = a * c0.z + b * s0.z;  r0.w = a * c0.w + b * s0.w;
    r1.x = a * c1.x + b * s1.x;  r1.y = a * c1.y + b * s1.y;
    r1.z = a * c1.z + b * s1.z;  r1.w = a * c1.w + b * s1.w;

    float4* __restrict__ po = reinterpret_cast<float4*>(out);
    po[i4]     = r0;
    po[i4 + 1] = r1;

    float4* gsw = reinterpret_cast<float4*>(g_sum);
    const float4 z = make_float4(0.f, 0.f, 0.f, 0.f);
    gsw[i4]     = z;                            // clean for next replay
    gsw[i4 + 1] = z;

    __syncthreads();                            // all g_cnt reads done
    if ((i & 15) == 0) {                        // one thread per class
        g_cnt[c] = 0.0f;
    }
}

// ---------------------------------------------------------------------------
// Launch. Inputs per metadata: embeded_preds [N*D], labels [N*C],
// center [C*D]. Output: updated_center [C*D] float32.
// ---------------------------------------------------------------------------
extern "C" void kernel_launch(void* const* d_in, const int* in_sizes, int n_in,
                              void* d_out, int out_size) {
    const float* preds  = (const float*)d_in[0];
    const float* labels = (const float*)d_in[1];
    const float* center = (const float*)d_in[2];
    float* out = (float*)d_out;

    (void)in_sizes; (void)n_in; (void)out_size;

    cl_scan_accum_kernel<<<NN, SCANT>>>(labels, preds);
    cl_finalize_kernel<<<(CC * DD / 8) / 256, 256>>>(center, out);
}